// round 5
// baseline (speedup 1.0000x reference)
#include <cuda_runtime.h>
#include <math.h>
#include <stdint.h>

#define T_DIM 512
#define B_DIM 64
#define IC 512
#define HC 512
#define L_DIM 2
#define K1 1024      // IC + HC (weight row stride)
#define N1 1024      // 2 * HC
#define NB 128       // serial-kernel blocks (<= 148 SMs -> co-resident)
#define NT 256       // threads per block

#define OUT_ACT ((size_t)T_DIM * B_DIM * HC)

// ---------------- device-global scratch (allocation-free rule) ----------------
__device__ float g_act [(size_t)T_DIM * B_DIM * HC];   // layer-1 activations
__device__ float g_pre1[(size_t)T_DIM * B_DIM * N1];   // hoisted x@W1x^T + b1
__device__ float g_pre2[(size_t)T_DIM * B_DIM * HC];   // hoisted x@W2x^T + b2
__device__ float g_h [B_DIM * HC];
__device__ float g_rh[B_DIM * HC];
__device__ float g_z [B_DIM * HC];
__device__ unsigned g_bar_cnt = 0;
__device__ unsigned g_bar_gen = 0;

// Grid barrier with bounded spin: a true deadlock degrades to a wrong answer
// that terminates (device never left wedged).
__device__ __forceinline__ void grid_bar() {
    __syncthreads();
    if (threadIdx.x == 0) {
        __threadfence();
        unsigned gen = atomicAdd(&g_bar_gen, 0u);  // read generation BEFORE arriving
        __threadfence();
        unsigned t = atomicAdd(&g_bar_cnt, 1u);
        if (t == NB - 1) {
            atomicExch(&g_bar_cnt, 0u);
            __threadfence();
            atomicExch(&g_bar_gen, gen + 1u);
        } else {
            for (long it = 0; atomicAdd(&g_bar_gen, 0u) == gen; ++it) {
                if (it > (1L << 18)) break;   // ~50 ms escape hatch
                __nanosleep(128);
            }
        }
    }
    __syncthreads();
}

__device__ __forceinline__ float sigmoidf_(float v) {
    return 1.0f / (1.0f + expf(-v));
}

// =====================================================================
// Hoist kernel: for layer l, pre1 = lin @ W1x^T + b1 (N=1024) and
// pre2 = lin @ W2x^T + b2 (N=512) as one [32768 x 512] x [512 x 1536] GEMM.
// lin = x (l=0) or g_act (l=1). Classic 64x64x16 smem-tiled fp32 GEMM.
// grid: (24 n-tiles, 512 m-tiles), 256 threads, 4x4 micro-tile.
// =====================================================================
#define GBM 64
#define GBN 64
#define GBK 16

__global__ void __launch_bounds__(256)
hoist_kernel(const float* __restrict__ x,
             const float* __restrict__ W1, const float* __restrict__ b1,
             const float* __restrict__ W2, const float* __restrict__ b2,
             int l)
{
    __shared__ float sA[GBK][GBM + 4];
    __shared__ float sB[GBK][GBN + 4];

    const float* lin = (l == 0) ? x : g_act;

    const int bn  = blockIdx.x;          // 0..23
    const int m0  = blockIdx.y * GBM;    // row tile base (t*64+b space)
    const int tid = threadIdx.x;
    const int tx  = tid & 15;
    const int ty  = tid >> 4;

    const float* Wp;  const float* bp;  float* outp;  int n_stride;  int n0;
    if (bn < 16) {
        n0 = bn * GBN;
        Wp = W1 + (size_t)l * N1 * K1 + (size_t)n0 * K1;
        bp = b1 + l * N1 + n0;
        outp = g_pre1;  n_stride = N1;
    } else {
        n0 = (bn - 16) * GBN;
        Wp = W2 + (size_t)l * HC * K1 + (size_t)n0 * K1;
        bp = b2 + l * HC + n0;
        outp = g_pre2;  n_stride = HC;
    }

    const int lrow = tid >> 2;          // 0..63
    const int lk4  = (tid & 3) << 2;    // 0,4,8,12

    float acc[4][4];
    #pragma unroll
    for (int i = 0; i < 4; ++i)
        #pragma unroll
        for (int j = 0; j < 4; ++j) acc[i][j] = 0.f;

    for (int kt = 0; kt < IC; kt += GBK) {
        float4 a4 = *(const float4*)(lin + (size_t)(m0 + lrow) * IC + kt + lk4);
        float4 w4 = *(const float4*)(Wp  + (size_t)lrow * K1 + kt + lk4);
        __syncthreads();   // previous iteration's compute done
        sA[lk4 + 0][lrow] = a4.x;  sA[lk4 + 1][lrow] = a4.y;
        sA[lk4 + 2][lrow] = a4.z;  sA[lk4 + 3][lrow] = a4.w;
        sB[lk4 + 0][lrow] = w4.x;  sB[lk4 + 1][lrow] = w4.y;
        sB[lk4 + 2][lrow] = w4.z;  sB[lk4 + 3][lrow] = w4.w;
        __syncthreads();
        #pragma unroll
        for (int k = 0; k < GBK; ++k) {
            float4 av = *(const float4*)&sA[k][ty << 2];
            float4 bv = *(const float4*)&sB[k][tx << 2];
            acc[0][0] += av.x * bv.x;  acc[0][1] += av.x * bv.y;
            acc[0][2] += av.x * bv.z;  acc[0][3] += av.x * bv.w;
            acc[1][0] += av.y * bv.x;  acc[1][1] += av.y * bv.y;
            acc[1][2] += av.y * bv.z;  acc[1][3] += av.y * bv.w;
            acc[2][0] += av.z * bv.x;  acc[2][1] += av.z * bv.y;
            acc[2][2] += av.z * bv.z;  acc[2][3] += av.z * bv.w;
            acc[3][0] += av.w * bv.x;  acc[3][1] += av.w * bv.y;
            acc[3][2] += av.w * bv.z;  acc[3][3] += av.w * bv.w;
        }
    }

    #pragma unroll
    for (int i = 0; i < 4; ++i) {
        size_t m = (size_t)(m0 + (ty << 2) + i);
        #pragma unroll
        for (int j = 0; j < 4; ++j) {
            int nl = (tx << 2) + j;
            outp[m * n_stride + n0 + nl] = acc[i][j] + bp[nl];
        }
    }
}

// =====================================================================
// Serial kernel: per layer, 512 recurrent steps. Phases only carry the
// h / (r*h) contributions (K=512); x parts come pre-computed from g_pre*.
// =====================================================================
__global__ void __launch_bounds__(NT, 1)
serial_kernel(const float* __restrict__ hiddens,
              const float* __restrict__ W1, const float* __restrict__ W2,
              float* __restrict__ out, int l)
{
    __shared__ float ws1[8 * 512];      // this block's 8 GEMM1 rows (h-part)
    __shared__ float ws2[4 * 512];      // this block's 4 GEMM2 rows (h-part)
    __shared__ float xs[64 * 65];       // transposed activation chunk [k][b]

    const int tid = threadIdx.x;
    const int bid = blockIdx.x;

    float* lout = (l == 0) ? g_act : out;

    // Stage weight h-part rows once (reused all 512 steps)
    for (int i = tid; i < 8 * 512; i += NT) {
        int jj = i >> 9, k = i & 511;
        ws1[i] = W1[(size_t)l * N1 * K1 + (size_t)(bid * 8 + jj) * K1 + IC + k];
    }
    for (int i = tid; i < 4 * 512; i += NT) {
        int jj = i >> 9, k = i & 511;
        ws2[i] = W2[(size_t)l * HC * K1 + (size_t)(bid * 4 + jj) * K1 + IC + k];
    }

    // Init hidden state (broadcast over batch). NB*NT == B*HC.
    {
        int i = bid * NT + tid;
        g_h[i] = hiddens[l * HC + (i & (HC - 1))];
    }
    grid_bar();

    for (int t = 0; t < T_DIM; ++t) {
        // ---------- Phase 1: pre = pre1[t] + h @ W1h^T ; r, z ----------
        {
            const int b  = tid & 31;
            const int jj = tid >> 5;
            float acc0 = 0.f, acc1 = 0.f;
            const float* wrow = ws1 + jj * 512;

            for (int c = 0; c < 8; ++c) {
                #pragma unroll
                for (int r = 0; r < 16; ++r) {
                    int idx = r * NT + tid;
                    int bl = idx >> 6, kk = idx & 63;
                    xs[kk * 65 + bl] = g_h[bl * HC + (c << 6) + kk];
                }
                __syncthreads();
                const float* wc = wrow + (c << 6);
                #pragma unroll
                for (int kq = 0; kq < 16; ++kq) {
                    float4 w4 = *(const float4*)(wc + (kq << 2));
                    int base = (kq << 2) * 65;
                    acc0 += xs[base + b]            * w4.x;
                    acc1 += xs[base + b + 32]       * w4.x;
                    acc0 += xs[base + 65 + b]       * w4.y;
                    acc1 += xs[base + 65 + b + 32]  * w4.y;
                    acc0 += xs[base + 130 + b]      * w4.z;
                    acc1 += xs[base + 130 + b + 32] * w4.z;
                    acc0 += xs[base + 195 + b]      * w4.w;
                    acc1 += xs[base + 195 + b + 32] * w4.w;
                }
                __syncthreads();
            }

            int j = (bid << 3) + jj;
            float p0 = acc0 + g_pre1[((size_t)t * B_DIM + b)      * N1 + j];
            float p1 = acc1 + g_pre1[((size_t)t * B_DIM + b + 32) * N1 + j];
            if (j < HC) {              // r gate -> r*h
                g_rh[b * HC + j]        = sigmoidf_(p0) * g_h[b * HC + j];
                g_rh[(b + 32) * HC + j] = sigmoidf_(p1) * g_h[(b + 32) * HC + j];
            } else {                   // z gate
                int jz = j - HC;
                g_z[b * HC + jz]        = sigmoidf_(p0);
                g_z[(b + 32) * HC + jz] = sigmoidf_(p1);
            }
        }
        grid_bar();

        // ---------- Phase 2: g = tanh(pre2[t] + rh @ W2h^T) ; h update ----------
        {
            const int bb  = (tid & 31) + ((tid >> 7) << 5);  // 0..63
            const int jj2 = (tid >> 5) & 3;                  // 0..3
            float acc = 0.f;
            const float* wrow = ws2 + jj2 * 512;

            for (int c = 0; c < 8; ++c) {
                #pragma unroll
                for (int r = 0; r < 16; ++r) {
                    int idx = r * NT + tid;
                    int bl = idx >> 6, kk = idx & 63;
                    xs[kk * 65 + bl] = g_rh[bl * HC + (c << 6) + kk];
                }
                __syncthreads();
                const float* wc = wrow + (c << 6);
                #pragma unroll
                for (int kq = 0; kq < 16; ++kq) {
                    float4 w4 = *(const float4*)(wc + (kq << 2));
                    int base = (kq << 2) * 65;
                    acc += xs[base + bb]       * w4.x;
                    acc += xs[base + 65 + bb]  * w4.y;
                    acc += xs[base + 130 + bb] * w4.z;
                    acc += xs[base + 195 + bb] * w4.w;
                }
                __syncthreads();
            }

            int j2 = (bid << 2) + jj2;
            float g  = tanhf(acc + g_pre2[((size_t)t * B_DIM + bb) * HC + j2]);
            float z  = g_z[bb * HC + j2];
            float ho = g_h[bb * HC + j2];
            float hn = z * ho + (1.f - z) * g;
            g_h[bb * HC + j2] = hn;
            lout[((size_t)t * B_DIM + bb) * HC + j2] = hn;
        }
        grid_bar();
    }

    // final hidden for this layer
    {
        int i = bid * NT + tid;
        out[OUT_ACT + (size_t)l * B_DIM * HC + i] = g_h[i];
    }
    grid_bar();   // before next layer's kernels touch g_h / g_act
}

extern "C" void kernel_launch(void* const* d_in, const int* in_sizes, int n_in,
                              void* d_out, int out_size) {
    const float* x       = (const float*)d_in[0];
    const float* hiddens = (const float*)d_in[1];
    const float* W1      = (const float*)d_in[2];
    const float* b1      = (const float*)d_in[3];
    const float* W2      = (const float*)d_in[4];
    const float* b2      = (const float*)d_in[5];
    float* out = (float*)d_out;

    for (int l = 0; l < L_DIM; ++l) {
        hoist_kernel<<<dim3(24, 512), 256>>>(x, W1, b1, W2, b2, l);
        serial_kernel<<<NB, NT>>>(hiddens, W1, W2, out, l);
    }
}

// round 6
// speedup vs baseline: 1.1554x; 1.1554x over previous
#include <cuda_runtime.h>
#include <math.h>
#include <stdint.h>

#define T_DIM 512
#define B_DIM 64
#define IC 512
#define HC 512
#define L_DIM 2
#define K1 1024      // IC + HC (weight row stride)
#define N1 1024      // 2 * HC
#define NB 128       // serial blocks (1 CTA/SM, co-resident on 148 SMs)
#define NT 256       // threads per block (8 warps)

#define OUT_ACT ((size_t)T_DIM * B_DIM * HC)

// ---------------- device-global scratch (allocation-free rule) ----------------
__device__ float g_act [(size_t)T_DIM * B_DIM * HC];   // layer-1 activations
__device__ float g_pre1[(size_t)T_DIM * B_DIM * N1];   // hoisted x@W1x^T + b1
__device__ float g_pre2[(size_t)T_DIM * B_DIM * HC];   // hoisted x@W2x^T + b2
__device__ float g_h [B_DIM * HC];                     // [b][j]
__device__ float g_rh[B_DIM * HC];
__device__ float g_z [B_DIM * HC];
__device__ unsigned g_bar_cnt = 0;
__device__ unsigned g_bar_gen = 0;

// Grid barrier with bounded spin (a real deadlock degrades to a terminating
// wrong answer, never a wedged device).
__device__ __forceinline__ void grid_bar() {
    __syncthreads();
    if (threadIdx.x == 0) {
        __threadfence();
        unsigned gen = atomicAdd(&g_bar_gen, 0u);
        __threadfence();
        unsigned t = atomicAdd(&g_bar_cnt, 1u);
        if (t == NB - 1) {
            atomicExch(&g_bar_cnt, 0u);
            __threadfence();
            atomicExch(&g_bar_gen, gen + 1u);
        } else {
            for (long it = 0; atomicAdd(&g_bar_gen, 0u) == gen; ++it) {
                if (it > (1L << 19)) break;   // escape hatch
                __nanosleep(64);
            }
        }
    }
    __syncthreads();
}

// =====================================================================
// Hoist kernel: pre1 = lin @ W1x^T + b1 (N=1024), pre2 = lin @ W2x^T + b2
// (N=512) as one [32768 x 512] x [512 x 1536] GEMM.
// 128x64x16 block tile, 8x4 microtile, double-buffered smem.
// grid (24 n-tiles, 256 m-tiles), 256 threads.
// =====================================================================
#define HBM 128
#define HBN 64
#define HBK 16

__global__ void __launch_bounds__(256)
hoist_kernel(const float* __restrict__ x,
             const float* __restrict__ W1, const float* __restrict__ b1,
             const float* __restrict__ W2, const float* __restrict__ b2,
             int l)
{
    __shared__ float sA[2][HBK][HBM + 4];
    __shared__ float sB[2][HBK][HBN + 4];

    const float* lin = (l == 0) ? x : g_act;
    const int bn  = blockIdx.x;
    const int m0  = blockIdx.y * HBM;
    const int tid = threadIdx.x;

    const float* Wp;  const float* bp;  float* outp;  int n_stride;  int n0;
    if (bn < 16) {
        n0 = bn * HBN;
        Wp = W1 + (size_t)l * N1 * K1 + (size_t)n0 * K1;
        bp = b1 + l * N1 + n0;
        outp = g_pre1;  n_stride = N1;
    } else {
        n0 = (bn - 16) * HBN;
        Wp = W2 + (size_t)l * HC * K1 + (size_t)n0 * K1;
        bp = b2 + l * HC + n0;
        outp = g_pre2;  n_stride = HC;
    }

    const int lrow = tid >> 2;         // 0..63
    const int lk   = (tid & 3) << 2;   // 0,4,8,12
    const int tx   = tid & 15;         // n: tx*4
    const int ty   = tid >> 4;         // m: ty*8

    float acc[8][4];
    #pragma unroll
    for (int i = 0; i < 8; ++i)
        #pragma unroll
        for (int j = 0; j < 4; ++j) acc[i][j] = 0.f;

    // prefetch tile 0
    {
        float4 a0 = *(const float4*)(lin + (size_t)(m0 + lrow) * IC + lk);
        float4 a1 = *(const float4*)(lin + (size_t)(m0 + lrow + 64) * IC + lk);
        float4 b0 = *(const float4*)(Wp + (size_t)lrow * K1 + lk);
        sA[0][lk+0][lrow] = a0.x; sA[0][lk+1][lrow] = a0.y;
        sA[0][lk+2][lrow] = a0.z; sA[0][lk+3][lrow] = a0.w;
        sA[0][lk+0][lrow+64] = a1.x; sA[0][lk+1][lrow+64] = a1.y;
        sA[0][lk+2][lrow+64] = a1.z; sA[0][lk+3][lrow+64] = a1.w;
        sB[0][lk+0][lrow] = b0.x; sB[0][lk+1][lrow] = b0.y;
        sB[0][lk+2][lrow] = b0.z; sB[0][lk+3][lrow] = b0.w;
    }
    __syncthreads();

    for (int kt = 0; kt < IC; kt += HBK) {
        const int cur  = (kt >> 4) & 1;
        const bool more = (kt + HBK) < IC;
        float4 na0, na1, nb0;
        if (more) {
            na0 = *(const float4*)(lin + (size_t)(m0 + lrow) * IC + kt + HBK + lk);
            na1 = *(const float4*)(lin + (size_t)(m0 + lrow + 64) * IC + kt + HBK + lk);
            nb0 = *(const float4*)(Wp + (size_t)lrow * K1 + kt + HBK + lk);
        }
        #pragma unroll
        for (int k = 0; k < HBK; ++k) {
            float4 av0 = *(const float4*)&sA[cur][k][ty * 8];
            float4 av1 = *(const float4*)&sA[cur][k][ty * 8 + 4];
            float4 bv  = *(const float4*)&sB[cur][k][tx * 4];
            float a[8] = {av0.x, av0.y, av0.z, av0.w, av1.x, av1.y, av1.z, av1.w};
            float b[4] = {bv.x, bv.y, bv.z, bv.w};
            #pragma unroll
            for (int i = 0; i < 8; ++i)
                #pragma unroll
                for (int j = 0; j < 4; ++j)
                    acc[i][j] = fmaf(a[i], b[j], acc[i][j]);
        }
        if (more) {
            const int nxt = cur ^ 1;
            sA[nxt][lk+0][lrow] = na0.x; sA[nxt][lk+1][lrow] = na0.y;
            sA[nxt][lk+2][lrow] = na0.z; sA[nxt][lk+3][lrow] = na0.w;
            sA[nxt][lk+0][lrow+64] = na1.x; sA[nxt][lk+1][lrow+64] = na1.y;
            sA[nxt][lk+2][lrow+64] = na1.z; sA[nxt][lk+3][lrow+64] = na1.w;
            sB[nxt][lk+0][lrow] = nb0.x; sB[nxt][lk+1][lrow] = nb0.y;
            sB[nxt][lk+2][lrow] = nb0.z; sB[nxt][lk+3][lrow] = nb0.w;
            __syncthreads();
        }
    }

    float4 bias = *(const float4*)(bp + tx * 4);
    #pragma unroll
    for (int i = 0; i < 8; ++i) {
        float4 o;
        o.x = acc[i][0] + bias.x;  o.y = acc[i][1] + bias.y;
        o.z = acc[i][2] + bias.z;  o.w = acc[i][3] + bias.w;
        *(float4*)(outp + (size_t)(m0 + ty * 8 + i) * n_stride + n0 + tx * 4) = o;
    }
}

// =====================================================================
// Serial kernel: 512 recurrent steps per layer; only h / (r*h) GEMMs
// (K=512) remain in the serial path. Warp-tiled, vector smem loads,
// FFMA:LDS >= 2, cross-warp k-split reduction in smem.
//   Phase 1: block = 32 j (jg1) x 16 b (bg1); warp: kh=w>>2 (256 k),
//            bq=w&3 (4 b); lane = j.
//   Phase 2: block = 32 j (jg2) x  8 b (bg2); warp: kq=w>>1 (128 k),
//            bq2=w&1 (4 b); lane = j.
// smem: wsT1q 64KB | wsT2q 64KB | hs1 32KB | hs2 16KB | red 4KB = 180KB
// =====================================================================
#define SER_SMEM_FLOATS (16384 + 16384 + 8192 + 4096 + 1024)
#define SER_SMEM_BYTES  (SER_SMEM_FLOATS * 4)

__global__ void __launch_bounds__(NT, 1)
serial_kernel(const float* __restrict__ hiddens,
              const float* __restrict__ W1, const float* __restrict__ W2,
              float* __restrict__ out, int l)
{
    extern __shared__ float sm[];
    float* wsT1 = sm;                 // [k4 128][j 32][kk 4]
    float* wsT2 = sm + 16384;         // [k4 128][j 32][kk 4]
    float* hs1  = sm + 32768;         // [b 16][k 512]
    float* hs2  = sm + 40960;         // [b 8][k 512]
    float* red  = sm + 45056;         // [warp 8][i 4][lane 32]

    const int tid  = threadIdx.x;
    const int bid  = blockIdx.x;
    const int w    = tid >> 5;
    const int lane = tid & 31;

    const int jg1 = bid >> 2;   // 0..31  (32 j)
    const int bg1 = bid & 3;    // 0..3   (16 b)
    const int jg2 = bid >> 3;   // 0..15  (32 j)
    const int bg2 = bid & 7;    // 0..7   (8 b)

    float* lout = (l == 0) ? g_act : out;

    // Stage transposed h-part weights once per layer: wsT[(k>>2)*128 + j*4 + (k&3)]
    for (int idx = tid; idx < 32 * 512; idx += NT) {
        int jl = idx >> 9, k = idx & 511;
        wsT1[(k >> 2) * 128 + jl * 4 + (k & 3)] =
            W1[((size_t)l * N1 + jg1 * 32 + jl) * K1 + IC + k];
        wsT2[(k >> 2) * 128 + jl * 4 + (k & 3)] =
            W2[((size_t)l * HC + jg2 * 32 + jl) * K1 + IC + k];
    }

    // Init hidden state (broadcast over batch). NB*NT == B*HC.
    { int i = bid * NT + tid; g_h[i] = hiddens[l * HC + (i & (HC - 1))]; }
    grid_bar();

    const float4* gh4  = (const float4*)g_h;
    const float4* grh4 = (const float4*)g_rh;
    float4* hs1v = (float4*)hs1;
    float4* hs2v = (float4*)hs2;

    for (int t = 0; t < T_DIM; ++t) {
        // ---- stage hs1 = g_h[bg1*16 .. +16][:]  (2048 float4) ----
        #pragma unroll
        for (int q = 0; q < 8; ++q) {
            int idx = q * NT + tid;
            hs1v[idx] = __ldcg(&gh4[(size_t)bg1 * 2048 + idx]);
        }
        __syncthreads();

        // ---- Phase 1 compute: h @ W1h^T partials ----
        {
            const int kh = w >> 2;     // 0..1
            const int bq = w & 3;      // 0..3
            float acc0 = 0.f, acc1 = 0.f, acc2 = 0.f, acc3 = 0.f;
            const float4* wq = (const float4*)wsT1 + kh * 64 * 32 + lane;
            const float4* xb = (const float4*)hs1 + (size_t)bq * 4 * 128 + kh * 64;
            #pragma unroll 4
            for (int k4 = 0; k4 < 64; ++k4) {
                float4 wv = wq[k4 * 32];
                float4 x0 = xb[k4];
                float4 x1 = xb[128 + k4];
                float4 x2 = xb[256 + k4];
                float4 x3 = xb[384 + k4];
                acc0 = fmaf(wv.x, x0.x, acc0); acc0 = fmaf(wv.y, x0.y, acc0);
                acc0 = fmaf(wv.z, x0.z, acc0); acc0 = fmaf(wv.w, x0.w, acc0);
                acc1 = fmaf(wv.x, x1.x, acc1); acc1 = fmaf(wv.y, x1.y, acc1);
                acc1 = fmaf(wv.z, x1.z, acc1); acc1 = fmaf(wv.w, x1.w, acc1);
                acc2 = fmaf(wv.x, x2.x, acc2); acc2 = fmaf(wv.y, x2.y, acc2);
                acc2 = fmaf(wv.z, x2.z, acc2); acc2 = fmaf(wv.w, x2.w, acc2);
                acc3 = fmaf(wv.x, x3.x, acc3); acc3 = fmaf(wv.y, x3.y, acc3);
                acc3 = fmaf(wv.z, x3.z, acc3); acc3 = fmaf(wv.w, x3.w, acc3);
            }
            red[w * 128 +  0 + lane] = acc0;
            red[w * 128 + 32 + lane] = acc1;
            red[w * 128 + 64 + lane] = acc2;
            red[w * 128 + 96 + lane] = acc3;
        }
        __syncthreads();

        // ---- Phase 1 epilogue: 2 outputs/thread (512 total) ----
        #pragma unroll
        for (int q = 0; q < 2; ++q) {
            int o  = q * NT + tid;
            int jl = o & 31, bl = o >> 5;        // bl 0..15
            int bq = bl >> 2, ii = bl & 3;
            float s = red[bq * 128 + ii * 32 + jl]
                    + red[(4 + bq) * 128 + ii * 32 + jl];
            int j = jg1 * 32 + jl;
            int b = bg1 * 16 + bl;
            float pre = s + g_pre1[((size_t)t * B_DIM + b) * N1 + j];
            float sg  = 1.f / (1.f + expf(-pre));
            if (jg1 < 16) {
                float hv = __ldcg(&g_h[b * HC + j]);
                g_rh[b * HC + j] = sg * hv;
            } else {
                g_z[b * HC + (j - HC)] = sg;
            }
        }
        grid_bar();

        // ---- stage hs2 = g_rh[bg2*8 .. +8][:]  (1024 float4) ----
        #pragma unroll
        for (int q = 0; q < 4; ++q) {
            int idx = q * NT + tid;
            hs2v[idx] = __ldcg(&grh4[(size_t)bg2 * 1024 + idx]);
        }
        __syncthreads();

        // ---- Phase 2 compute: rh @ W2h^T partials ----
        {
            const int kq  = w >> 1;    // 0..3
            const int bq2 = w & 1;     // 0..1
            float acc0 = 0.f, acc1 = 0.f, acc2 = 0.f, acc3 = 0.f;
            const float4* wq = (const float4*)wsT2 + kq * 32 * 32 + lane;
            const float4* xb = (const float4*)hs2 + (size_t)bq2 * 4 * 128 + kq * 32;
            #pragma unroll 4
            for (int k4 = 0; k4 < 32; ++k4) {
                float4 wv = wq[k4 * 32];
                float4 x0 = xb[k4];
                float4 x1 = xb[128 + k4];
                float4 x2 = xb[256 + k4];
                float4 x3 = xb[384 + k4];
                acc0 = fmaf(wv.x, x0.x, acc0); acc0 = fmaf(wv.y, x0.y, acc0);
                acc0 = fmaf(wv.z, x0.z, acc0); acc0 = fmaf(wv.w, x0.w, acc0);
                acc1 = fmaf(wv.x, x1.x, acc1); acc1 = fmaf(wv.y, x1.y, acc1);
                acc1 = fmaf(wv.z, x1.z, acc1); acc1 = fmaf(wv.w, x1.w, acc1);
                acc2 = fmaf(wv.x, x2.x, acc2); acc2 = fmaf(wv.y, x2.y, acc2);
                acc2 = fmaf(wv.z, x2.z, acc2); acc2 = fmaf(wv.w, x2.w, acc2);
                acc3 = fmaf(wv.x, x3.x, acc3); acc3 = fmaf(wv.y, x3.y, acc3);
                acc3 = fmaf(wv.z, x3.z, acc3); acc3 = fmaf(wv.w, x3.w, acc3);
            }
            red[w * 128 +  0 + lane] = acc0;
            red[w * 128 + 32 + lane] = acc1;
            red[w * 128 + 64 + lane] = acc2;
            red[w * 128 + 96 + lane] = acc3;
        }
        __syncthreads();

        // ---- Phase 2 epilogue: 1 output/thread (256 total) ----
        {
            int o  = tid;
            int jl = o & 31, bl = o >> 5;        // bl 0..7
            int bq2 = bl >> 2, ii = bl & 3;
            float s = red[(0 + bq2) * 128 + ii * 32 + jl]
                    + red[(2 + bq2) * 128 + ii * 32 + jl]
                    + red[(4 + bq2) * 128 + ii * 32 + jl]
                    + red[(6 + bq2) * 128 + ii * 32 + jl];
            int j = jg2 * 32 + jl;
            int b = bg2 * 8 + bl;
            float g  = tanhf(s + g_pre2[((size_t)t * B_DIM + b) * HC + j]);
            float z  = __ldcg(&g_z[b * HC + j]);
            float ho = __ldcg(&g_h[b * HC + j]);
            float hn = z * ho + (1.f - z) * g;
            g_h[b * HC + j] = hn;
            lout[((size_t)t * B_DIM + b) * HC + j] = hn;
        }
        grid_bar();
    }

    // final hidden for this layer
    { int i = bid * NT + tid;
      out[OUT_ACT + (size_t)l * B_DIM * HC + i] = __ldcg(&g_h[i]); }
    grid_bar();   // before next layer's kernels touch g_h / g_act
}

extern "C" void kernel_launch(void* const* d_in, const int* in_sizes, int n_in,
                              void* d_out, int out_size) {
    const float* x       = (const float*)d_in[0];
    const float* hiddens = (const float*)d_in[1];
    const float* W1      = (const float*)d_in[2];
    const float* b1      = (const float*)d_in[3];
    const float* W2      = (const float*)d_in[4];
    const float* b2      = (const float*)d_in[5];
    float* out = (float*)d_out;

    cudaFuncSetAttribute(serial_kernel,
                         cudaFuncAttributeMaxDynamicSharedMemorySize,
                         SER_SMEM_BYTES);

    for (int l = 0; l < L_DIM; ++l) {
        hoist_kernel<<<dim3(24, 256), 256>>>(x, W1, b1, W2, b2, l);
        serial_kernel<<<NB, NT, SER_SMEM_BYTES>>>(hiddens, W1, W2, out, l);
    }
}

// round 7
// speedup vs baseline: 2.0118x; 1.7412x over previous
#include <cuda_runtime.h>
#include <math.h>
#include <stdint.h>

#define T_DIM 512
#define B_DIM 64
#define IC 512
#define HC 512
#define L_DIM 2
#define K1 1024      // IC + HC (weight row stride)
#define N1 1024      // 2 * HC
#define NB 128       // serial blocks (1 CTA/SM, co-resident on 148 SMs)
#define NT 512       // serial threads per block (16 warps)

#define OUT_ACT ((size_t)T_DIM * B_DIM * HC)

// ---------------- device-global scratch (allocation-free rule) ----------------
__device__ float g_act [(size_t)T_DIM * B_DIM * HC];   // layer-1 activations
__device__ float g_pre1[(size_t)T_DIM * B_DIM * N1];   // hoisted x@W1x^T + b1
__device__ float g_pre2[(size_t)T_DIM * B_DIM * HC];   // hoisted x@W2x^T + b2
__device__ float g_h [B_DIM * HC];                     // [b][j]
__device__ float g_rh[B_DIM * HC];
__device__ float g_z [B_DIM * HC];
__device__ unsigned g_bar_cnt = 0;
__device__ unsigned g_bar_gen = 0;
__device__ unsigned g_dead    = 0;

__device__ __forceinline__ unsigned ld_u32_cg(const unsigned* p) {
    unsigned v;
    asm volatile("ld.global.cg.u32 %0, [%1];" : "=r"(v) : "l"(p) : "memory");
    return v;
}

// Grid barrier: arrivals = one atomicAdd per CTA; release = atomicExch of a
// monotonic epoch; waiters poll with PLAIN cg loads (no RMW contention, no
// nanosleep). Bounded spin -> terminating wrong answer, never a wedged device.
__device__ __forceinline__ void grid_bar(unsigned target) {
    __syncthreads();
    if (threadIdx.x == 0) {
        if (ld_u32_cg(&g_dead) == 0u) {
            __threadfence();                          // release my writes
            unsigned t = atomicAdd(&g_bar_cnt, 1u);
            if (t == NB - 1) {
                g_bar_cnt = 0;                        // safe: next arrivals gated on gen
                __threadfence();
                atomicExch(&g_bar_gen, target);
            } else {
                int it = 0;
                while (ld_u32_cg(&g_bar_gen) != target) {
                    if (++it > (1 << 20)) { atomicExch(&g_dead, 1u); break; }
                }
            }
            __threadfence();                          // acquire
        }
    }
    __syncthreads();
}

// =====================================================================
// Hoist kernel (unchanged from round 6): pre1 = lin @ W1x^T + b1,
// pre2 = lin @ W2x^T + b2 as one [32768 x 512] x [512 x 1536] GEMM.
// =====================================================================
#define HBM 128
#define HBN 64
#define HBK 16

__global__ void __launch_bounds__(256)
hoist_kernel(const float* __restrict__ x,
             const float* __restrict__ W1, const float* __restrict__ b1,
             const float* __restrict__ W2, const float* __restrict__ b2,
             int l)
{
    __shared__ float sA[2][HBK][HBM + 4];
    __shared__ float sB[2][HBK][HBN + 4];

    const float* lin = (l == 0) ? x : g_act;
    const int bn  = blockIdx.x;
    const int m0  = blockIdx.y * HBM;
    const int tid = threadIdx.x;

    const float* Wp;  const float* bp;  float* outp;  int n_stride;  int n0;
    if (bn < 16) {
        n0 = bn * HBN;
        Wp = W1 + (size_t)l * N1 * K1 + (size_t)n0 * K1;
        bp = b1 + l * N1 + n0;
        outp = g_pre1;  n_stride = N1;
    } else {
        n0 = (bn - 16) * HBN;
        Wp = W2 + (size_t)l * HC * K1 + (size_t)n0 * K1;
        bp = b2 + l * HC + n0;
        outp = g_pre2;  n_stride = HC;
    }

    const int lrow = tid >> 2;
    const int lk   = (tid & 3) << 2;
    const int tx   = tid & 15;
    const int ty   = tid >> 4;

    float acc[8][4];
    #pragma unroll
    for (int i = 0; i < 8; ++i)
        #pragma unroll
        for (int j = 0; j < 4; ++j) acc[i][j] = 0.f;

    {
        float4 a0 = *(const float4*)(lin + (size_t)(m0 + lrow) * IC + lk);
        float4 a1 = *(const float4*)(lin + (size_t)(m0 + lrow + 64) * IC + lk);
        float4 b0 = *(const float4*)(Wp + (size_t)lrow * K1 + lk);
        sA[0][lk+0][lrow] = a0.x; sA[0][lk+1][lrow] = a0.y;
        sA[0][lk+2][lrow] = a0.z; sA[0][lk+3][lrow] = a0.w;
        sA[0][lk+0][lrow+64] = a1.x; sA[0][lk+1][lrow+64] = a1.y;
        sA[0][lk+2][lrow+64] = a1.z; sA[0][lk+3][lrow+64] = a1.w;
        sB[0][lk+0][lrow] = b0.x; sB[0][lk+1][lrow] = b0.y;
        sB[0][lk+2][lrow] = b0.z; sB[0][lk+3][lrow] = b0.w;
    }
    __syncthreads();

    for (int kt = 0; kt < IC; kt += HBK) {
        const int cur  = (kt >> 4) & 1;
        const bool more = (kt + HBK) < IC;
        float4 na0, na1, nb0;
        if (more) {
            na0 = *(const float4*)(lin + (size_t)(m0 + lrow) * IC + kt + HBK + lk);
            na1 = *(const float4*)(lin + (size_t)(m0 + lrow + 64) * IC + kt + HBK + lk);
            nb0 = *(const float4*)(Wp + (size_t)lrow * K1 + kt + HBK + lk);
        }
        #pragma unroll
        for (int k = 0; k < HBK; ++k) {
            float4 av0 = *(const float4*)&sA[cur][k][ty * 8];
            float4 av1 = *(const float4*)&sA[cur][k][ty * 8 + 4];
            float4 bv  = *(const float4*)&sB[cur][k][tx * 4];
            float a[8] = {av0.x, av0.y, av0.z, av0.w, av1.x, av1.y, av1.z, av1.w};
            float b[4] = {bv.x, bv.y, bv.z, bv.w};
            #pragma unroll
            for (int i = 0; i < 8; ++i)
                #pragma unroll
                for (int j = 0; j < 4; ++j)
                    acc[i][j] = fmaf(a[i], b[j], acc[i][j]);
        }
        if (more) {
            const int nxt = cur ^ 1;
            sA[nxt][lk+0][lrow] = na0.x; sA[nxt][lk+1][lrow] = na0.y;
            sA[nxt][lk+2][lrow] = na0.z; sA[nxt][lk+3][lrow] = na0.w;
            sA[nxt][lk+0][lrow+64] = na1.x; sA[nxt][lk+1][lrow+64] = na1.y;
            sA[nxt][lk+2][lrow+64] = na1.z; sA[nxt][lk+3][lrow+64] = na1.w;
            sB[nxt][lk+0][lrow] = nb0.x; sB[nxt][lk+1][lrow] = nb0.y;
            sB[nxt][lk+2][lrow] = nb0.z; sB[nxt][lk+3][lrow] = nb0.w;
            __syncthreads();
        }
    }

    float4 bias = *(const float4*)(bp + tx * 4);
    #pragma unroll
    for (int i = 0; i < 8; ++i) {
        float4 o;
        o.x = acc[i][0] + bias.x;  o.y = acc[i][1] + bias.y;
        o.z = acc[i][2] + bias.z;  o.w = acc[i][3] + bias.w;
        *(float4*)(outp + (size_t)(m0 + ty * 8 + i) * n_stride + n0 + tx * 4) = o;
    }
}

// =====================================================================
// Serial kernel: 512 steps/layer, only h/(r*h) GEMMs (K=512) serial.
// 16 warps/CTA. Phase 1: block = 32 j (jg1) x 16 b (bg1); warp =
// (bq 0..3) x (kh 0..3: 128 k each). Phase 2: block = 32 j (jg2) x 8 b
// (bg2); warp = (bq2 0..1) x (kq 0..7: 64 k each). Cross-warp k-split
// reduced through smem. All recurrence-independent operands prefetched.
// smem: wsT1 64K | wsT2 64K | hs1 32K | hs2 16K | red 8K = 184KB
// =====================================================================
#define SER_SMEM_FLOATS (16384 + 16384 + 8192 + 4096 + 2048)
#define SER_SMEM_BYTES  (SER_SMEM_FLOATS * 4)

__global__ void __launch_bounds__(NT, 1)
serial_kernel(const float* __restrict__ hiddens,
              const float* __restrict__ W1, const float* __restrict__ W2,
              float* __restrict__ out, int l)
{
    extern __shared__ float sm[];
    float* wsT1 = sm;                 // [k4 128][j 32][kk 4]
    float* wsT2 = sm + 16384;         // [k4 128][j 32][kk 4]
    float* hs1  = sm + 32768;         // [b 16][k 512]
    float* hs2  = sm + 40960;         // [b 8][k 512]
    float* red  = sm + 45056;         // [warp 16][i 4][lane 32]

    const int tid  = threadIdx.x;
    const int bid  = blockIdx.x;
    const int wp   = tid >> 5;
    const int lane = tid & 31;

    const int jg1 = bid >> 2;   // 0..31
    const int bg1 = bid & 3;    // 0..3
    const int jg2 = bid >> 3;   // 0..15
    const int bg2 = bid & 7;    // 0..7

    float* lout = (l == 0) ? g_act : out;

    // Per-thread output coordinates (fixed across steps)
    const int jl1 = tid & 31, bl1 = tid >> 5 & 15;      // phase1: 512 outputs
    const int j1  = jg1 * 32 + jl1;
    const int b1o = bg1 * 16 + bl1;
    const int jl2 = tid & 31, bl2 = (tid >> 5) & 7;     // phase2: 256 outputs
    const int j2  = jg2 * 32 + jl2;
    const int b2o = bg2 * 8 + bl2;
    const bool p2own = (tid < 256);

    // Stage transposed h-part weights once per layer
    for (int idx = tid; idx < 32 * 512; idx += NT) {
        int jl = idx >> 9, k = idx & 511;
        wsT1[(k >> 2) * 128 + jl * 4 + (k & 3)] =
            W1[((size_t)l * N1 + jg1 * 32 + jl) * K1 + IC + k];
        wsT2[(k >> 2) * 128 + jl * 4 + (k & 3)] =
            W2[((size_t)l * HC + jg2 * 32 + jl) * K1 + IC + k];
    }

    // Init hidden state (broadcast over batch)
    { int i = bid * NT + tid;
      if (i < B_DIM * HC) g_h[i] = hiddens[l * HC + (i & (HC - 1))]; }

    unsigned ep = ld_u32_cg(&g_bar_gen);   // epoch base for this launch
    grid_bar(++ep);

    const float4* gh4  = (const float4*)g_h;
    const float4* grh4 = (const float4*)g_rh;
    float4* hs1v = (float4*)hs1;
    float4* hs2v = (float4*)hs2;

    for (int t = 0; t < T_DIM; ++t) {
        // ---- stage hs1 = g_h[bg1*16..+16][:] and prefetch t-only operands ----
        #pragma unroll
        for (int q = 0; q < 4; ++q) {
            int idx = q * NT + tid;
            hs1v[idx] = __ldcg(&gh4[(size_t)bg1 * 2048 + idx]);
        }
        float pre1v = __ldcg(&g_pre1[((size_t)t * B_DIM + b1o) * N1 + j1]);
        float pre2v = 0.f, hov = 0.f;
        if (p2own) {
            pre2v = __ldcg(&g_pre2[((size_t)t * B_DIM + b2o) * HC + j2]);
            hov   = __ldcg(&g_h[b2o * HC + j2]);
        }
        __syncthreads();

        // ---- Phase 1 compute: h @ W1h^T partials ----
        {
            const int bq = wp >> 2;    // 0..3
            const int kh = wp & 3;     // 0..3 -> k4 in [kh*32, kh*32+32)
            float a0 = 0.f, a1 = 0.f, a2 = 0.f, a3 = 0.f;
            const float4* wq = (const float4*)wsT1 + (kh * 32) * 32 + lane;
            const float4* x0p = hs1v + (size_t)(bq * 4 + 0) * 128 + kh * 32;
            const float4* x1p = x0p + 128;
            const float4* x2p = x0p + 256;
            const float4* x3p = x0p + 384;
            #pragma unroll 8
            for (int k4 = 0; k4 < 32; ++k4) {
                float4 wv = wq[k4 * 32];
                float4 x0 = x0p[k4], x1 = x1p[k4], x2 = x2p[k4], x3 = x3p[k4];
                a0 = fmaf(wv.x, x0.x, a0); a0 = fmaf(wv.y, x0.y, a0);
                a0 = fmaf(wv.z, x0.z, a0); a0 = fmaf(wv.w, x0.w, a0);
                a1 = fmaf(wv.x, x1.x, a1); a1 = fmaf(wv.y, x1.y, a1);
                a1 = fmaf(wv.z, x1.z, a1); a1 = fmaf(wv.w, x1.w, a1);
                a2 = fmaf(wv.x, x2.x, a2); a2 = fmaf(wv.y, x2.y, a2);
                a2 = fmaf(wv.z, x2.z, a2); a2 = fmaf(wv.w, x2.w, a2);
                a3 = fmaf(wv.x, x3.x, a3); a3 = fmaf(wv.y, x3.y, a3);
                a3 = fmaf(wv.z, x3.z, a3); a3 = fmaf(wv.w, x3.w, a3);
            }
            red[wp * 128 +  0 + lane] = a0;
            red[wp * 128 + 32 + lane] = a1;
            red[wp * 128 + 64 + lane] = a2;
            red[wp * 128 + 96 + lane] = a3;
        }
        __syncthreads();

        // ---- Phase 1 epilogue: 1 output/thread ----
        {
            int bq_ = bl1 >> 2, ii = bl1 & 3;
            float s = red[(bq_ * 4 + 0) * 128 + ii * 32 + jl1]
                    + red[(bq_ * 4 + 1) * 128 + ii * 32 + jl1]
                    + red[(bq_ * 4 + 2) * 128 + ii * 32 + jl1]
                    + red[(bq_ * 4 + 3) * 128 + ii * 32 + jl1];
            float pre = s + pre1v;
            float sg  = 1.f / (1.f + expf(-pre));
            if (jg1 < 16) {
                float hv = hs1[bl1 * 512 + j1];        // h from smem stage
                g_rh[b1o * HC + j1] = sg * hv;
            } else {
                g_z[b1o * HC + (j1 - HC)] = sg;
            }
        }
        grid_bar(++ep);

        // ---- stage hs2 = g_rh[bg2*8..+8][:] ; prefetch z ----
        #pragma unroll
        for (int q = 0; q < 2; ++q) {
            int idx = q * NT + tid;
            hs2v[idx] = __ldcg(&grh4[(size_t)bg2 * 1024 + idx]);
        }
        float zv = 0.f;
        if (p2own) zv = __ldcg(&g_z[b2o * HC + j2]);
        __syncthreads();

        // ---- Phase 2 compute: rh @ W2h^T partials ----
        {
            const int bq2 = wp >> 3;   // 0..1
            const int kq  = wp & 7;    // 0..7 -> k4 in [kq*16, kq*16+16)
            float a0 = 0.f, a1 = 0.f, a2 = 0.f, a3 = 0.f;
            const float4* wq = (const float4*)wsT2 + (kq * 16) * 32 + lane;
            const float4* x0p = hs2v + (size_t)(bq2 * 4 + 0) * 128 + kq * 16;
            const float4* x1p = x0p + 128;
            const float4* x2p = x0p + 256;
            const float4* x3p = x0p + 384;
            #pragma unroll 8
            for (int k4 = 0; k4 < 16; ++k4) {
                float4 wv = wq[k4 * 32];
                float4 x0 = x0p[k4], x1 = x1p[k4], x2 = x2p[k4], x3 = x3p[k4];
                a0 = fmaf(wv.x, x0.x, a0); a0 = fmaf(wv.y, x0.y, a0);
                a0 = fmaf(wv.z, x0.z, a0); a0 = fmaf(wv.w, x0.w, a0);
                a1 = fmaf(wv.x, x1.x, a1); a1 = fmaf(wv.y, x1.y, a1);
                a1 = fmaf(wv.z, x1.z, a1); a1 = fmaf(wv.w, x1.w, a1);
                a2 = fmaf(wv.x, x2.x, a2); a2 = fmaf(wv.y, x2.y, a2);
                a2 = fmaf(wv.z, x2.z, a2); a2 = fmaf(wv.w, x2.w, a2);
                a3 = fmaf(wv.x, x3.x, a3); a3 = fmaf(wv.y, x3.y, a3);
                a3 = fmaf(wv.z, x3.z, a3); a3 = fmaf(wv.w, x3.w, a3);
            }
            red[wp * 128 +  0 + lane] = a0;
            red[wp * 128 + 32 + lane] = a1;
            red[wp * 128 + 64 + lane] = a2;
            red[wp * 128 + 96 + lane] = a3;
        }
        __syncthreads();

        // ---- Phase 2 epilogue: threads 0..255 ----
        if (p2own) {
            int bq2_ = bl2 >> 2, ii = bl2 & 3;
            float s = 0.f;
            #pragma unroll
            for (int kq = 0; kq < 8; ++kq)
                s += red[(bq2_ * 8 + kq) * 128 + ii * 32 + jl2];
            float g  = tanhf(s + pre2v);
            float hn = zv * hov + (1.f - zv) * g;
            g_h[b2o * HC + j2] = hn;
            lout[((size_t)t * B_DIM + b2o) * HC + j2] = hn;
        }
        grid_bar(++ep);
    }

    // final hidden for this layer
    { int i = bid * NT + tid;
      if (i < B_DIM * HC)
          out[OUT_ACT + (size_t)l * B_DIM * HC + i] = __ldcg(&g_h[i]); }
    grid_bar(++ep);   // before next layer's kernels touch g_h / g_act
}

extern "C" void kernel_launch(void* const* d_in, const int* in_sizes, int n_in,
                              void* d_out, int out_size) {
    const float* x       = (const float*)d_in[0];
    const float* hiddens = (const float*)d_in[1];
    const float* W1      = (const float*)d_in[2];
    const float* b1      = (const float*)d_in[3];
    const float* W2      = (const float*)d_in[4];
    const float* b2      = (const float*)d_in[5];
    float* out = (float*)d_out;

    cudaFuncSetAttribute(serial_kernel,
                         cudaFuncAttributeMaxDynamicSharedMemorySize,
                         SER_SMEM_BYTES);

    for (int l = 0; l < L_DIM; ++l) {
        hoist_kernel<<<dim3(24, 256), 256>>>(x, W1, b1, W2, b2, l);
        serial_kernel<<<NB, NT, SER_SMEM_BYTES>>>(hiddens, W1, W2, out, l);
    }
}

// round 8
// speedup vs baseline: 2.1052x; 1.0464x over previous
#include <cuda_runtime.h>
#include <cuda_bf16.h>
#include <math.h>
#include <stdint.h>

#define T_DIM 512
#define B_DIM 64
#define IC 512
#define HC 512
#define L_DIM 2
#define K1 1024      // IC + HC (weight row stride)
#define N1 1024      // 2 * HC
#define NB 128       // serial blocks (1 CTA/SM, co-resident)
#define NT 512       // serial threads per block (16 warps)

#define M_ALL (T_DIM * B_DIM)          // 32768
#define N_ALL (N1 + HC)                // 1536

#define OUT_ACT ((size_t)T_DIM * B_DIM * HC)

// ---------------- device-global scratch (allocation-free rule) ----------------
__device__ float g_act [(size_t)T_DIM * B_DIM * HC];
__device__ float g_pre1[(size_t)T_DIM * B_DIM * N1];
__device__ float g_pre2[(size_t)T_DIM * B_DIM * HC];
__device__ float g_h [B_DIM * HC];
__device__ float g_rh[B_DIM * HC];
__device__ float g_z [B_DIM * HC];
__device__ __nv_bfloat16 g_ahi[(size_t)M_ALL * IC];
__device__ __nv_bfloat16 g_alo[(size_t)M_ALL * IC];
__device__ __nv_bfloat16 g_whi[(size_t)N_ALL * IC];
__device__ __nv_bfloat16 g_wlo[(size_t)N_ALL * IC];
__device__ unsigned g_bar_cnt = 0;
__device__ unsigned g_bar_gen = 0;
__device__ unsigned g_dead    = 0;

__device__ __forceinline__ unsigned ld_u32_cg(const unsigned* p) {
    unsigned v;
    asm volatile("ld.global.cg.u32 %0, [%1];" : "=r"(v) : "l"(p) : "memory");
    return v;
}

// Grid barrier: atomic arrivals, epoch release, plain-load pollers, bounded spin.
__device__ __forceinline__ void grid_bar(unsigned target) {
    __syncthreads();
    if (threadIdx.x == 0) {
        if (ld_u32_cg(&g_dead) == 0u) {
            __threadfence();
            unsigned t = atomicAdd(&g_bar_cnt, 1u);
            if (t == NB - 1) {
                g_bar_cnt = 0;
                __threadfence();
                atomicExch(&g_bar_gen, target);
            } else {
                int it = 0;
                while (ld_u32_cg(&g_bar_gen) != target) {
                    if (++it > (1 << 20)) { atomicExch(&g_dead, 1u); break; }
                }
            }
            __threadfence();
        }
    }
    __syncthreads();
}

// =====================================================================
// Split-conversion kernels: fp32 -> (bf16 hi, bf16 lo) with lo = v - hi.
// =====================================================================
__device__ __forceinline__ void split4(float4 v, uint2& hi, uint2& lo) {
    __nv_bfloat16 h0 = __float2bfloat16_rn(v.x);
    __nv_bfloat16 h1 = __float2bfloat16_rn(v.y);
    __nv_bfloat16 h2 = __float2bfloat16_rn(v.z);
    __nv_bfloat16 h3 = __float2bfloat16_rn(v.w);
    __nv_bfloat16 l0 = __float2bfloat16_rn(v.x - __bfloat162float(h0));
    __nv_bfloat16 l1 = __float2bfloat16_rn(v.y - __bfloat162float(h1));
    __nv_bfloat16 l2 = __float2bfloat16_rn(v.z - __bfloat162float(h2));
    __nv_bfloat16 l3 = __float2bfloat16_rn(v.w - __bfloat162float(h3));
    hi.x = (unsigned)__bfloat16_as_ushort(h0) | ((unsigned)__bfloat16_as_ushort(h1) << 16);
    hi.y = (unsigned)__bfloat16_as_ushort(h2) | ((unsigned)__bfloat16_as_ushort(h3) << 16);
    lo.x = (unsigned)__bfloat16_as_ushort(l0) | ((unsigned)__bfloat16_as_ushort(l1) << 16);
    lo.y = (unsigned)__bfloat16_as_ushort(l2) | ((unsigned)__bfloat16_as_ushort(l3) << 16);
}

__global__ void __launch_bounds__(256)
conv_act(const float* __restrict__ x, int l)
{
    const float* lin = (l == 0) ? x : g_act;
    size_t i = (size_t)blockIdx.x * 256 + threadIdx.x;   // over float4; exact grid
    float4 v = ((const float4*)lin)[i];
    uint2 hi, lo;
    split4(v, hi, lo);
    ((uint2*)g_ahi)[i] = hi;
    ((uint2*)g_alo)[i] = lo;
}

__global__ void __launch_bounds__(256)
conv_w(const float* __restrict__ W1, const float* __restrict__ W2, int l)
{
    size_t i = (size_t)blockIdx.x * 256 + threadIdx.x;   // over float4 (196608)
    int n  = (int)(i >> 7);        // 0..1535 (row), 128 float4 per row
    int k4 = (int)(i & 127);
    const float* src = (n < N1)
        ? (W1 + (size_t)l * N1 * K1 + (size_t)n * K1 + k4 * 4)
        : (W2 + (size_t)l * HC * K1 + (size_t)(n - N1) * K1 + k4 * 4);
    float4 v = *(const float4*)src;
    uint2 hi, lo;
    split4(v, hi, lo);
    ((uint2*)g_whi)[(size_t)n * 128 + k4] = hi;
    ((uint2*)g_wlo)[(size_t)n * 128 + k4] = lo;
}

// =====================================================================
// mma hoist: pre = lin @ Wx^T + b via bf16 two-term split on tensor cores.
// C[32768, 1536] = sum of 3 bf16 GEMM terms (hi*hi + hi*lo + lo*hi), fp32 acc.
// Block tile 128x64x32, 256 threads (8 warps = 4m x 2n of 32x32 warp tiles),
// double-buffered smem, mma.sync.m16n8k16.bf16.
// =====================================================================
#define MBM 128
#define MBN 64
#define MBK 32
#define SAPAD 40   // smem row stride in halfs (80B: 16B-aligned, conflict-free frags)

__device__ __forceinline__ void mma16816(float* c, const unsigned* a, const unsigned* b) {
    asm volatile(
        "mma.sync.aligned.m16n8k16.row.col.f32.bf16.bf16.f32 "
        "{%0,%1,%2,%3}, {%4,%5,%6,%7}, {%8,%9}, {%0,%1,%2,%3};\n"
        : "+f"(c[0]), "+f"(c[1]), "+f"(c[2]), "+f"(c[3])
        : "r"(a[0]), "r"(a[1]), "r"(a[2]), "r"(a[3]), "r"(b[0]), "r"(b[1]));
}

__global__ void __launch_bounds__(256)
mma_hoist(const float* __restrict__ b1, const float* __restrict__ b2, int l)
{
    __shared__ __nv_bfloat16 sA[2][MBM][SAPAD];
    __shared__ __nv_bfloat16 sB[2][MBN][SAPAD];

    const int bn  = blockIdx.x;            // 0..23
    const int m0  = blockIdx.y * MBM;      // 0..32640
    const int tid = threadIdx.x;
    const int wid = tid >> 5, lane = tid & 31;
    const int wm  = wid & 3;               // m: wm*32
    const int wn  = wid >> 2;              // n: wn*32

    float* outp;  const float* bp;  int nstr, n0, wrow0;
    if (bn < 16) { n0 = bn * MBN;        wrow0 = n0;       outp = g_pre1; nstr = N1; bp = b1 + l * N1 + n0; }
    else         { n0 = (bn - 16) * MBN; wrow0 = N1 + n0;  outp = g_pre2; nstr = HC; bp = b2 + l * HC + n0; }

    const __nv_bfloat16* segA[3] = { g_ahi, g_ahi, g_alo };
    const __nv_bfloat16* segW[3] = { g_whi, g_wlo, g_whi };

    const int ar = tid >> 2;               // A/W load row
    const int aq = (tid & 3) * 8;          // half-offset of uint4 within 32-half row chunk

    float acc[2][4][4];
    #pragma unroll
    for (int mt = 0; mt < 2; ++mt)
        #pragma unroll
        for (int nt = 0; nt < 4; ++nt)
            #pragma unroll
            for (int q = 0; q < 4; ++q) acc[mt][nt][q] = 0.f;

    // preload it=0
    {
        const __nv_bfloat16* A = segA[0];
        const __nv_bfloat16* W = segW[0];
        uint4 a0 = *(const uint4*)(A + (size_t)(m0 + ar) * IC + aq);
        uint4 a1 = *(const uint4*)(A + (size_t)(m0 + ar + 64) * IC + aq);
        uint4 w0 = *(const uint4*)(W + (size_t)(wrow0 + ar) * IC + aq);
        *(uint4*)&sA[0][ar][aq]      = a0;
        *(uint4*)&sA[0][ar + 64][aq] = a1;
        *(uint4*)&sB[0][ar][aq]      = w0;
    }
    __syncthreads();

    const int NIT = 48;                     // 3 segments x 16 k-tiles
    for (int it = 0; it < NIT; ++it) {
        const int cur = it & 1;
        const bool more = (it + 1) < NIT;
        uint4 na0, na1, nw0;
        if (more) {
            int seg = (it + 1) >> 4;
            int kt  = ((it + 1) & 15) * MBK;
            const __nv_bfloat16* A = segA[seg];
            const __nv_bfloat16* W = segW[seg];
            na0 = *(const uint4*)(A + (size_t)(m0 + ar) * IC + kt + aq);
            na1 = *(const uint4*)(A + (size_t)(m0 + ar + 64) * IC + kt + aq);
            nw0 = *(const uint4*)(W + (size_t)(wrow0 + ar) * IC + kt + aq);
        }

        #pragma unroll
        for (int ks = 0; ks < MBK; ks += 16) {
            const int kb = ks + (lane & 3) * 2;
            unsigned af[2][4], bf[4][2];
            #pragma unroll
            for (int mt = 0; mt < 2; ++mt) {
                int r = wm * 32 + mt * 16 + (lane >> 2);
                af[mt][0] = *(const unsigned*)&sA[cur][r][kb];
                af[mt][1] = *(const unsigned*)&sA[cur][r + 8][kb];
                af[mt][2] = *(const unsigned*)&sA[cur][r][kb + 8];
                af[mt][3] = *(const unsigned*)&sA[cur][r + 8][kb + 8];
            }
            #pragma unroll
            for (int nt = 0; nt < 4; ++nt) {
                int c = wn * 32 + nt * 8 + (lane >> 2);
                bf[nt][0] = *(const unsigned*)&sB[cur][c][kb];
                bf[nt][1] = *(const unsigned*)&sB[cur][c][kb + 8];
            }
            #pragma unroll
            for (int mt = 0; mt < 2; ++mt)
                #pragma unroll
                for (int nt = 0; nt < 4; ++nt)
                    mma16816(acc[mt][nt], af[mt], bf[nt]);
        }

        if (more) {
            const int nxt = cur ^ 1;
            *(uint4*)&sA[nxt][ar][aq]      = na0;
            *(uint4*)&sA[nxt][ar + 64][aq] = na1;
            *(uint4*)&sB[nxt][ar][aq]      = nw0;
            __syncthreads();
        }
    }

    // epilogue: +bias, fp32 stores
    #pragma unroll
    for (int mt = 0; mt < 2; ++mt) {
        #pragma unroll
        for (int nt = 0; nt < 4; ++nt) {
            int r  = m0 + wm * 32 + mt * 16 + (lane >> 2);
            int cl = wn * 32 + nt * 8 + (lane & 3) * 2;
            float bx = bp[cl], by = bp[cl + 1];
            float2 o0 = { acc[mt][nt][0] + bx, acc[mt][nt][1] + by };
            float2 o1 = { acc[mt][nt][2] + bx, acc[mt][nt][3] + by };
            *(float2*)(outp + (size_t)r * nstr + n0 + cl)       = o0;
            *(float2*)(outp + (size_t)(r + 8) * nstr + n0 + cl) = o1;
        }
    }
}

// =====================================================================
// Serial kernel (unchanged structure from round 7; fast transcendentals).
// =====================================================================
#define SER_SMEM_FLOATS (16384 + 16384 + 8192 + 4096 + 2048)
#define SER_SMEM_BYTES  (SER_SMEM_FLOATS * 4)

__global__ void __launch_bounds__(NT, 1)
serial_kernel(const float* __restrict__ hiddens,
              const float* __restrict__ W1, const float* __restrict__ W2,
              float* __restrict__ out, int l)
{
    extern __shared__ float sm[];
    float* wsT1 = sm;                 // [k4 128][j 32][kk 4]
    float* wsT2 = sm + 16384;
    float* hs1  = sm + 32768;         // [b 16][k 512]
    float* hs2  = sm + 40960;         // [b 8][k 512]
    float* red  = sm + 45056;         // [warp 16][i 4][lane 32]

    const int tid  = threadIdx.x;
    const int bid  = blockIdx.x;
    const int wp   = tid >> 5;
    const int lane = tid & 31;

    const int jg1 = bid >> 2;
    const int bg1 = bid & 3;
    const int jg2 = bid >> 3;
    const int bg2 = bid & 7;

    float* lout = (l == 0) ? g_act : out;

    const int jl1 = tid & 31, bl1 = (tid >> 5) & 15;
    const int j1  = jg1 * 32 + jl1;
    const int b1o = bg1 * 16 + bl1;
    const int jl2 = tid & 31, bl2 = (tid >> 5) & 7;
    const int j2  = jg2 * 32 + jl2;
    const int b2o = bg2 * 8 + bl2;
    const bool p2own = (tid < 256);

    for (int idx = tid; idx < 32 * 512; idx += NT) {
        int jl = idx >> 9, k = idx & 511;
        wsT1[(k >> 2) * 128 + jl * 4 + (k & 3)] =
            W1[((size_t)l * N1 + jg1 * 32 + jl) * K1 + IC + k];
        wsT2[(k >> 2) * 128 + jl * 4 + (k & 3)] =
            W2[((size_t)l * HC + jg2 * 32 + jl) * K1 + IC + k];
    }

    { int i = bid * NT + tid;
      if (i < B_DIM * HC) g_h[i] = hiddens[l * HC + (i & (HC - 1))]; }

    unsigned ep = ld_u32_cg(&g_bar_gen);
    grid_bar(++ep);

    const float4* gh4  = (const float4*)g_h;
    const float4* grh4 = (const float4*)g_rh;
    float4* hs1v = (float4*)hs1;
    float4* hs2v = (float4*)hs2;

    for (int t = 0; t < T_DIM; ++t) {
        #pragma unroll
        for (int q = 0; q < 4; ++q) {
            int idx = q * NT + tid;
            hs1v[idx] = __ldcg(&gh4[(size_t)bg1 * 2048 + idx]);
        }
        float pre1v = __ldcg(&g_pre1[((size_t)t * B_DIM + b1o) * N1 + j1]);
        float pre2v = 0.f, hov = 0.f;
        if (p2own) {
            pre2v = __ldcg(&g_pre2[((size_t)t * B_DIM + b2o) * HC + j2]);
            hov   = __ldcg(&g_h[b2o * HC + j2]);
        }
        __syncthreads();

        {
            const int bq = wp >> 2;
            const int kh = wp & 3;
            float a0 = 0.f, a1 = 0.f, a2 = 0.f, a3 = 0.f;
            const float4* wq = (const float4*)wsT1 + (kh * 32) * 32 + lane;
            const float4* x0p = hs1v + (size_t)(bq * 4 + 0) * 128 + kh * 32;
            const float4* x1p = x0p + 128;
            const float4* x2p = x0p + 256;
            const float4* x3p = x0p + 384;
            #pragma unroll 8
            for (int k4 = 0; k4 < 32; ++k4) {
                float4 wv = wq[k4 * 32];
                float4 x0 = x0p[k4], x1 = x1p[k4], x2 = x2p[k4], x3 = x3p[k4];
                a0 = fmaf(wv.x, x0.x, a0); a0 = fmaf(wv.y, x0.y, a0);
                a0 = fmaf(wv.z, x0.z, a0); a0 = fmaf(wv.w, x0.w, a0);
                a1 = fmaf(wv.x, x1.x, a1); a1 = fmaf(wv.y, x1.y, a1);
                a1 = fmaf(wv.z, x1.z, a1); a1 = fmaf(wv.w, x1.w, a1);
                a2 = fmaf(wv.x, x2.x, a2); a2 = fmaf(wv.y, x2.y, a2);
                a2 = fmaf(wv.z, x2.z, a2); a2 = fmaf(wv.w, x2.w, a2);
                a3 = fmaf(wv.x, x3.x, a3); a3 = fmaf(wv.y, x3.y, a3);
                a3 = fmaf(wv.z, x3.z, a3); a3 = fmaf(wv.w, x3.w, a3);
            }
            red[wp * 128 +  0 + lane] = a0;
            red[wp * 128 + 32 + lane] = a1;
            red[wp * 128 + 64 + lane] = a2;
            red[wp * 128 + 96 + lane] = a3;
        }
        __syncthreads();

        {
            int bq_ = bl1 >> 2, ii = bl1 & 3;
            float s = red[(bq_ * 4 + 0) * 128 + ii * 32 + jl1]
                    + red[(bq_ * 4 + 1) * 128 + ii * 32 + jl1]
                    + red[(bq_ * 4 + 2) * 128 + ii * 32 + jl1]
                    + red[(bq_ * 4 + 3) * 128 + ii * 32 + jl1];
            float pre = s + pre1v;
            float sg  = __fdividef(1.f, 1.f + __expf(-pre));
            if (jg1 < 16) {
                float hv = hs1[bl1 * 512 + j1];
                g_rh[b1o * HC + j1] = sg * hv;
            } else {
                g_z[b1o * HC + (j1 - HC)] = sg;
            }
        }
        grid_bar(++ep);

        #pragma unroll
        for (int q = 0; q < 2; ++q) {
            int idx = q * NT + tid;
            hs2v[idx] = __ldcg(&grh4[(size_t)bg2 * 1024 + idx]);
        }
        float zv = 0.f;
        if (p2own) zv = __ldcg(&g_z[b2o * HC + j2]);
        __syncthreads();

        {
            const int bq2 = wp >> 3;
            const int kq  = wp & 7;
            float a0 = 0.f, a1 = 0.f, a2 = 0.f, a3 = 0.f;
            const float4* wq = (const float4*)wsT2 + (kq * 16) * 32 + lane;
            const float4* x0p = hs2v + (size_t)(bq2 * 4 + 0) * 128 + kq * 16;
            const float4* x1p = x0p + 128;
            const float4* x2p = x0p + 256;
            const float4* x3p = x0p + 384;
            #pragma unroll 8
            for (int k4 = 0; k4 < 16; ++k4) {
                float4 wv = wq[k4 * 32];
                float4 x0 = x0p[k4], x1 = x1p[k4], x2 = x2p[k4], x3 = x3p[k4];
                a0 = fmaf(wv.x, x0.x, a0); a0 = fmaf(wv.y, x0.y, a0);
                a0 = fmaf(wv.z, x0.z, a0); a0 = fmaf(wv.w, x0.w, a0);
                a1 = fmaf(wv.x, x1.x, a1); a1 = fmaf(wv.y, x1.y, a1);
                a1 = fmaf(wv.z, x1.z, a1); a1 = fmaf(wv.w, x1.w, a1);
                a2 = fmaf(wv.x, x2.x, a2); a2 = fmaf(wv.y, x2.y, a2);
                a2 = fmaf(wv.z, x2.z, a2); a2 = fmaf(wv.w, x2.w, a2);
                a3 = fmaf(wv.x, x3.x, a3); a3 = fmaf(wv.y, x3.y, a3);
                a3 = fmaf(wv.z, x3.z, a3); a3 = fmaf(wv.w, x3.w, a3);
            }
            red[wp * 128 +  0 + lane] = a0;
            red[wp * 128 + 32 + lane] = a1;
            red[wp * 128 + 64 + lane] = a2;
            red[wp * 128 + 96 + lane] = a3;
        }
        __syncthreads();

        if (p2own) {
            int bq2_ = bl2 >> 2, ii = bl2 & 3;
            float s = 0.f;
            #pragma unroll
            for (int kq = 0; kq < 8; ++kq)
                s += red[(bq2_ * 8 + kq) * 128 + ii * 32 + jl2];
            float x2v = s + pre2v;
            float g  = 1.f - __fdividef(2.f, __expf(2.f * x2v) + 1.f);
            float hn = zv * hov + (1.f - zv) * g;
            g_h[b2o * HC + j2] = hn;
            lout[((size_t)t * B_DIM + b2o) * HC + j2] = hn;
        }
        grid_bar(++ep);
    }

    { int i = bid * NT + tid;
      if (i < B_DIM * HC)
          out[OUT_ACT + (size_t)l * B_DIM * HC + i] = __ldcg(&g_h[i]); }
    grid_bar(++ep);
}

extern "C" void kernel_launch(void* const* d_in, const int* in_sizes, int n_in,
                              void* d_out, int out_size) {
    const float* x       = (const float*)d_in[0];
    const float* hiddens = (const float*)d_in[1];
    const float* W1      = (const float*)d_in[2];
    const float* b1      = (const float*)d_in[3];
    const float* W2      = (const float*)d_in[4];
    const float* b2      = (const float*)d_in[5];
    float* out = (float*)d_out;

    cudaFuncSetAttribute(serial_kernel,
                         cudaFuncAttributeMaxDynamicSharedMemorySize,
                         SER_SMEM_BYTES);

    for (int l = 0; l < L_DIM; ++l) {
        conv_act<<<M_ALL * IC / 4 / 256, 256>>>(x, l);          // 16384 blocks
        conv_w  <<<N_ALL * IC / 4 / 256, 256>>>(W1, W2, l);     // 768 blocks
        mma_hoist<<<dim3(24, M_ALL / MBM), 256>>>(b1, b2, l);   // 24 x 256
        serial_kernel<<<NB, NT, SER_SMEM_BYTES>>>(hiddens, W1, W2, out, l);
    }
}